// round 1
// baseline (speedup 1.0000x reference)
#include <cuda_runtime.h>

#define BATCH 16384
#define DIM   128
#define NREL  500
#define ALPHA 0.001f

// global accumulators: 0=sum(h^2) 1=sum(t^2) 2=sum(||R||^2 per elem) 3=sum sq err
__device__ float g_acc[4];

__global__ void zero_kernel() {
    if (threadIdx.x < 4) g_acc[threadIdx.x] = 0.0f;
}

__device__ __forceinline__ float warpSum(float v) {
#pragma unroll
    for (int o = 16; o > 0; o >>= 1) v += __shfl_xor_sync(0xffffffffu, v, o);
    return v;
}

extern __shared__ float smem[];

// One block per relation. SMEM: R (16384 f), match list (16384 i), h staging (8*4*128 f)
__global__ __launch_bounds__(256, 1) void rescal_kernel(
    const int*   __restrict__ h_idx,
    const int*   __restrict__ r_idx,
    const int*   __restrict__ t_idx,
    const float* __restrict__ labels,
    const float* __restrict__ ent_w,
    const float* __restrict__ rel_w,
    float*       __restrict__ out)
{
    float* sR    = smem;                       // 16384 floats (64KB)
    int*   sList = (int*)(smem + 16384);       // 16384 ints  (64KB)
    float* sH    = smem + 16384 + 16384;       // 8 warps * 4 elems * 128 floats (16KB)

    __shared__ int   sCount;
    __shared__ float sRn2, sH2, sT2, sE2;

    const int tid  = threadIdx.x;
    const int lane = tid & 31;
    const int warp = tid >> 5;
    const int rel  = blockIdx.x;

    if (tid == 0) { sCount = 0; sRn2 = 0.f; sH2 = 0.f; sT2 = 0.f; sE2 = 0.f; }
    __syncthreads();

    // ---- Load relation matrix R [128x128] into SMEM, accumulate ||R||^2 ----
    const float4* Rg  = (const float4*)rel_w + (size_t)rel * 4096;
    float4*       sR4 = (float4*)sR;
    float r2 = 0.f;
#pragma unroll 4
    for (int i = tid; i < 4096; i += 256) {
        float4 v = Rg[i];
        sR4[i] = v;
        r2 += v.x * v.x + v.y * v.y + v.z * v.z + v.w * v.w;
    }
    r2 = warpSum(r2);
    if (lane == 0) atomicAdd(&sRn2, r2);

    // ---- Scan r_idx, build match list (L2-resident, 64KB per block) ----
    for (int i = tid; i < BATCH; i += 256) {
        if (r_idx[i] == rel) {
            int p = atomicAdd(&sCount, 1);
            sList[p] = i;
        }
    }
    __syncthreads();
    const int count = sCount;

    float h2 = 0.f, t2 = 0.f, sq = 0.f;
    float* myH = sH + warp * (4 * 128);

    // ---- Each warp: 4 batch elements per pass over SMEM R ----
    for (int base = warp * 4; base < count; base += 8 * 4) {
        const int ne = min(4, count - base);

        float4 tq[4];
        float  s[4];
#pragma unroll
        for (int e = 0; e < 4; e++) { s[e] = 0.f; tq[e] = make_float4(0.f, 0.f, 0.f, 0.f); }

        for (int e = 0; e < ne; e++) {
            int i = sList[base + e];
            const float4* tv = (const float4*)(ent_w + (size_t)t_idx[i] * DIM);
            const float4* hv = (const float4*)(ent_w + (size_t)h_idx[i] * DIM);
            float4 tv4 = tv[lane];
            float4 hv4 = hv[lane];
            tq[e] = tv4;
            t2 += tv4.x * tv4.x + tv4.y * tv4.y + tv4.z * tv4.z + tv4.w * tv4.w;
            h2 += hv4.x * hv4.x + hv4.y * hv4.y + hv4.z * hv4.z + hv4.w * hv4.w;
            ((float4*)(myH + e * 128))[lane] = hv4;
        }
        __syncwarp();

        // score_e = sum_j h_e[j] * (R[j,:] . t_e)  ; lane owns columns 4l..4l+3
#pragma unroll 2
        for (int j = 0; j < DIM; j++) {
            float4 rq = sR4[j * 32 + lane];
#pragma unroll
            for (int e = 0; e < 4; e++) {
                float tmp = rq.x * tq[e].x + rq.y * tq[e].y + rq.z * tq[e].z + rq.w * tq[e].w;
                s[e] += myH[e * 128 + j] * tmp;   // broadcast LDS
            }
        }
        __syncwarp();

        for (int e = 0; e < ne; e++) {
            float val = warpSum(s[e]);
            if (lane == 0) {
                int i = sList[base + e];
                out[1 + i] = val;
                float d = val - labels[i];
                sq += d * d;
            }
        }
    }

    // ---- Block reduction of loss partials, 4 global atomics per block ----
    h2 = warpSum(h2);
    t2 = warpSum(t2);
    sq = warpSum(sq);
    if (lane == 0) {
        atomicAdd(&sH2, h2);
        atomicAdd(&sT2, t2);
        atomicAdd(&sE2, sq);
    }
    __syncthreads();
    if (tid == 0) {
        atomicAdd(&g_acc[0], sH2);
        atomicAdd(&g_acc[1], sT2);
        atomicAdd(&g_acc[2], sRn2 * (float)count);  // each of `count` elems contributes ||R||^2
        atomicAdd(&g_acc[3], sE2);
    }
}

__global__ void finalize_kernel(float* __restrict__ out) {
    const float invBD = 1.0f / ((float)BATCH * (float)DIM);
    const float invBDD = 1.0f / ((float)BATCH * (float)DIM * (float)DIM);
    float norms = (g_acc[0] * invBD + g_acc[1] * invBD + g_acc[2] * invBDD) * (1.0f / 3.0f);
    out[0] = g_acc[3] / (float)BATCH + ALPHA * norms;
}

extern "C" void kernel_launch(void* const* d_in, const int* in_sizes, int n_in,
                              void* d_out, int out_size)
{
    const int*   h_idx  = (const int*)d_in[0];
    const int*   r_idx  = (const int*)d_in[1];
    const int*   t_idx  = (const int*)d_in[2];
    const float* labels = (const float*)d_in[3];
    const float* ent_w  = (const float*)d_in[4];
    const float* rel_w  = (const float*)d_in[5];
    float*       out    = (float*)d_out;

    const size_t smem_bytes = (16384 + 16384 + 8 * 4 * 128) * sizeof(float); // 147456
    cudaFuncSetAttribute(rescal_kernel,
                         cudaFuncAttributeMaxDynamicSharedMemorySize,
                         (int)smem_bytes);

    zero_kernel<<<1, 32>>>();
    rescal_kernel<<<NREL, 256, smem_bytes>>>(h_idx, r_idx, t_idx, labels,
                                             ent_w, rel_w, out);
    finalize_kernel<<<1, 1>>>(out);
}

// round 2
// speedup vs baseline: 1.3335x; 1.3335x over previous
#include <cuda_runtime.h>

#define BATCH 16384
#define DIM   128
#define NREL  500
#define MAXC  2048
#define ALPHA 0.001f

// Global scratch (sanctioned __device__ arrays):
// g_acc: 0=sum(h^2) 1=sum(t^2) 2=sum(||R||^2 per batch elem) 3=sum sq err
__device__ float g_acc[4];
__device__ int   g_cnt[NREL];
__device__ int   g_bucket[NREL * MAXC];

__global__ void zero_kernel() {
    int t = threadIdx.x;
    if (t < 4) g_acc[t] = 0.0f;
    for (int i = t; i < NREL; i += blockDim.x) g_cnt[i] = 0;
}

__global__ void bucket_kernel(const int* __restrict__ r_idx) {
    int i = blockIdx.x * blockDim.x + threadIdx.x;
    if (i < BATCH) {
        int rel  = r_idx[i];
        int slot = atomicAdd(&g_cnt[rel], 1);
        if (slot < MAXC) g_bucket[rel * MAXC + slot] = i;
    }
}

__device__ __forceinline__ float warpSum(float v) {
#pragma unroll
    for (int o = 16; o > 0; o >>= 1) v += __shfl_xor_sync(0xffffffffu, v, o);
    return v;
}

__device__ __forceinline__ float comp4(const float4 v, int d) {
    return d == 0 ? v.x : d == 1 ? v.y : d == 2 ? v.z : v.w;
}

extern __shared__ float smem[];   // R: 16384 floats = 64KB

// One block per relation, 128 threads (4 warps), 3 CTAs/SM.
__global__ __launch_bounds__(128, 3) void rescal_main(
    const int*   __restrict__ h_idx,
    const int*   __restrict__ t_idx,
    const float* __restrict__ labels,
    const float* __restrict__ ent_w,
    const float* __restrict__ rel_w,
    float*       __restrict__ out)
{
    __shared__ float sH2, sT2, sE2, sR2;

    const int tid  = threadIdx.x;
    const int lane = tid & 31;
    const int warp = tid >> 5;
    const int rel  = blockIdx.x;

    if (tid == 0) { sH2 = 0.f; sT2 = 0.f; sE2 = 0.f; sR2 = 0.f; }

    // ---- Load R [128x128] into SMEM, accumulate ||R||^2 ----
    const float4* Rg  = (const float4*)rel_w + (size_t)rel * 4096;
    float4*       sR4 = (float4*)smem;
    float r2 = 0.f;
#pragma unroll 8
    for (int i = tid; i < 4096; i += 128) {
        float4 v = Rg[i];
        sR4[i] = v;
        r2 += v.x * v.x + v.y * v.y + v.z * v.z + v.w * v.w;
    }
    r2 = warpSum(r2);
    if (lane == 0) atomicAdd(&sR2, r2);

    int count = g_cnt[rel];
    if (count > MAXC) count = MAXC;
    __syncthreads();

    const int* bucket = g_bucket + (size_t)rel * MAXC;
    float h2 = 0.f, t2 = 0.f, sq = 0.f;

    // ---- Each warp: 8 batch elements per pass over SMEM R ----
    for (int base = warp * 8; base < count; base += 4 * 8) {
        const int ne = min(8, count - base);

        float4 hq[8], tq[8], y[8];
        int    idx[8];
#pragma unroll
        for (int e = 0; e < 8; e++) {
            y[e] = make_float4(0.f, 0.f, 0.f, 0.f);
            if (e < ne) {
                int i = bucket[base + e];
                idx[e] = i;
                float4 hv = ((const float4*)(ent_w + (size_t)h_idx[i] * DIM))[lane];
                float4 tv = ((const float4*)(ent_w + (size_t)t_idx[i] * DIM))[lane];
                hq[e] = hv; tq[e] = tv;
                h2 += hv.x * hv.x + hv.y * hv.y + hv.z * hv.z + hv.w * hv.w;
                t2 += tv.x * tv.x + tv.y * tv.y + tv.z * tv.z + tv.w * tv.w;
            } else {
                idx[e] = -1;
                hq[e] = make_float4(0.f, 0.f, 0.f, 0.f);
                tq[e] = make_float4(0.f, 0.f, 0.f, 0.f);
            }
        }

        // y_c[e] = sum_j h_j[e] * R[j, c]   (lane owns columns 4*lane..4*lane+3)
        for (int jc = 0; jc < 32; jc++) {
#pragma unroll
            for (int d = 0; d < 4; d++) {
                float4 rq = sR4[(jc * 4 + d) * 32 + lane];
#pragma unroll
                for (int e = 0; e < 8; e++) {
                    float hj = __shfl_sync(0xffffffffu, comp4(hq[e], d), jc);
                    y[e].x += rq.x * hj;
                    y[e].y += rq.y * hj;
                    y[e].z += rq.z * hj;
                    y[e].w += rq.w * hj;
                }
            }
        }

        // score[e] = sum_c y_c[e] * t_c[e]
#pragma unroll
        for (int e = 0; e < 8; e++) {
            if (e < ne) {
                float p = y[e].x * tq[e].x + y[e].y * tq[e].y +
                          y[e].z * tq[e].z + y[e].w * tq[e].w;
                p = warpSum(p);
                if (lane == 0) {
                    int i = idx[e];
                    out[1 + i] = p;
                    float df = p - labels[i];
                    sq += df * df;
                }
            }
        }
    }

    // ---- Loss partial reduction: per-warp then 4 global atomics per block ----
    h2 = warpSum(h2);
    t2 = warpSum(t2);
    sq = warpSum(sq);
    if (lane == 0) {
        atomicAdd(&sH2, h2);
        atomicAdd(&sT2, t2);
        atomicAdd(&sE2, sq);
    }
    __syncthreads();
    if (tid == 0) {
        atomicAdd(&g_acc[0], sH2);
        atomicAdd(&g_acc[1], sT2);
        atomicAdd(&g_acc[2], sR2 * (float)count);
        atomicAdd(&g_acc[3], sE2);
    }
}

__global__ void finalize_kernel(float* __restrict__ out) {
    const float invBD  = 1.0f / ((float)BATCH * (float)DIM);
    const float invBDD = 1.0f / ((float)BATCH * (float)DIM * (float)DIM);
    float norms = (g_acc[0] * invBD + g_acc[1] * invBD + g_acc[2] * invBDD) * (1.0f / 3.0f);
    out[0] = g_acc[3] / (float)BATCH + ALPHA * norms;
}

extern "C" void kernel_launch(void* const* d_in, const int* in_sizes, int n_in,
                              void* d_out, int out_size)
{
    const int*   h_idx  = (const int*)d_in[0];
    const int*   r_idx  = (const int*)d_in[1];
    const int*   t_idx  = (const int*)d_in[2];
    const float* labels = (const float*)d_in[3];
    const float* ent_w  = (const float*)d_in[4];
    const float* rel_w  = (const float*)d_in[5];
    float*       out    = (float*)d_out;

    const int smem_bytes = 16384 * sizeof(float);   // 64KB
    cudaFuncSetAttribute(rescal_main,
                         cudaFuncAttributeMaxDynamicSharedMemorySize, smem_bytes);

    zero_kernel<<<1, 512>>>();
    bucket_kernel<<<(BATCH + 255) / 256, 256>>>(r_idx);
    rescal_main<<<NREL, 128, smem_bytes>>>(h_idx, t_idx, labels, ent_w, rel_w, out);
    finalize_kernel<<<1, 1>>>(out);
}

// round 6
// speedup vs baseline: 1.7229x; 1.2920x over previous
#include <cuda_runtime.h>
#include <cuda_bf16.h>
#include <cstdint>

#define BATCH 16384
#define DIM   128
#define NREL  500
#define MAXC  2048
#define ALPHA 0.001f

#define KP  136          // padded K (bf16 elems) for R/T tiles
#define KPB 272          // bytes per row (136*2)
#define HP  132          // H row stride in floats

// 0=sum(h^2) 1=sum(t^2) 2=sum(||R||^2 * count) 3=sum sq err
__device__ float g_acc[4];
__device__ int   g_cnt[NREL];
__device__ int   g_bucket[NREL * MAXC];

// ---- smem layout (bytes) ----
#define OFF_RHI 0
#define OFF_RLO (128 * KPB)                       // 34816
#define OFF_T   (2 * 128 * KPB)                   // 69632; per warp: hi then lo
#define T_WARP  (16 * KPB * 2)                    // 8704
#define OFF_H   (OFF_T + 4 * T_WARP)              // 104448; per warp 16*HP*4
#define H_WARP  (16 * HP * 4)                     // 8448
#define SMEM_TOTAL (OFF_H + 4 * H_WARP)           // 138240

extern __shared__ char smem[];

__device__ __forceinline__ float warpSum(float v) {
#pragma unroll
    for (int o = 16; o > 0; o >>= 1) v += __shfl_xor_sync(0xffffffffu, v, o);
    return v;
}

// split-convert 2 floats into hi/lo bf16 pairs
__device__ __forceinline__ void split2(float x, float y,
                                       __nv_bfloat162& hi, __nv_bfloat162& lo) {
    hi = __floats2bfloat162_rn(x, y);
    lo = __floats2bfloat162_rn(x - __bfloat162float(hi.x),
                               y - __bfloat162float(hi.y));
}

__device__ __forceinline__ void mma_bf16(float& c0, float& c1, float& c2, float& c3,
                                         uint32_t a0, uint32_t a1, uint32_t a2, uint32_t a3,
                                         uint32_t b0, uint32_t b1) {
    asm volatile(
        "mma.sync.aligned.m16n8k16.row.col.f32.bf16.bf16.f32 "
        "{%0,%1,%2,%3}, {%4,%5,%6,%7}, {%8,%9}, {%0,%1,%2,%3};"
        : "+f"(c0), "+f"(c1), "+f"(c2), "+f"(c3)
        : "r"(a0), "r"(a1), "r"(a2), "r"(a3), "r"(b0), "r"(b1));
}

__global__ void bucket_kernel(const int* __restrict__ r_idx) {
    int i = blockIdx.x * blockDim.x + threadIdx.x;
    if (i < BATCH) {
        int rel  = r_idx[i];
        int slot = atomicAdd(&g_cnt[rel], 1);
        if (slot < MAXC) g_bucket[rel * MAXC + slot] = i;
    }
}

__global__ __launch_bounds__(128, 1) void rescal_main(
    const int*   __restrict__ h_idx,
    const int*   __restrict__ t_idx,
    const float* __restrict__ labels,
    const float* __restrict__ ent_w,
    const float* __restrict__ rel_w,
    float*       __restrict__ out)
{
    __shared__ float sH2, sT2, sE2, sR2;

    const int tid  = threadIdx.x;
    const int lane = tid & 31;
    const int wid  = tid >> 5;
    const int rel  = blockIdx.x;

    char* Rhi = smem + OFF_RHI;
    char* Rlo = smem + OFF_RLO;
    char* Thi = smem + OFF_T + wid * T_WARP;
    char* Tlo = Thi + 16 * KPB;
    float* Hw = (float*)(smem + OFF_H + wid * H_WARP);

    if (tid == 0) { sH2 = 0.f; sT2 = 0.f; sE2 = 0.f; sR2 = 0.f; }
    __syncthreads();

    // ---- R [128x128] fp32 -> bf16 hi/lo split tiles in smem; ||R||^2 ----
    const float4* Rg = (const float4*)rel_w + (size_t)rel * 4096;
    float r2 = 0.f;
#pragma unroll 4
    for (int it = 0; it < 32; it++) {
        int i   = it * 128 + tid;
        int row = i >> 5;
        int col = (i & 31) * 4;
        float4 v = Rg[i];
        r2 += v.x * v.x + v.y * v.y + v.z * v.z + v.w * v.w;
        __nv_bfloat162 h0, l0, h1, l1;
        split2(v.x, v.y, h0, l0);
        split2(v.z, v.w, h1, l1);
        char* ph = Rhi + row * KPB + col * 2;
        char* pl = Rlo + row * KPB + col * 2;
        *(__nv_bfloat162*)(ph)     = h0;
        *(__nv_bfloat162*)(ph + 4) = h1;
        *(__nv_bfloat162*)(pl)     = l0;
        *(__nv_bfloat162*)(pl + 4) = l1;
    }
    r2 = warpSum(r2);
    if (lane == 0) atomicAdd(&sR2, r2);

    int count = g_cnt[rel];
    if (count > MAXC) count = MAXC;
    const int* bucket = g_bucket + (size_t)rel * MAXC;
    __syncthreads();

    float h2 = 0.f, t2 = 0.f, sq = 0.f;

    const int gr  = lane >> 2;   // 0..7
    const int tig = lane & 3;    // 0..3

    // ---- per-warp chunks of 16 batch elements (warps fully independent) ----
    for (int base = wid * 16; base < count; base += 64) {
        const int ne = min(16, count - base);

        // gather: 2 lanes per row, 64 elements (= 16 float4) each
        {
            const int r    = lane >> 1;
            const int half = lane & 1;
            if (r < ne) {
                int i = bucket[base + r];
                const float4* tv = (const float4*)(ent_w + (size_t)t_idx[i] * DIM) + half * 16;
                const float4* hv = (const float4*)(ent_w + (size_t)h_idx[i] * DIM) + half * 16;
                char*  pth = Thi + r * KPB + half * 64 * 2;   // 64 bf16 = 128 bytes
                char*  ptl = Tlo + r * KPB + half * 64 * 2;
                float* phh = Hw + r * HP + half * 64;
#pragma unroll 4
                for (int f = 0; f < 16; f++) {
                    float4 t4 = tv[f];
                    float4 h4 = hv[f];
                    t2 += t4.x * t4.x + t4.y * t4.y + t4.z * t4.z + t4.w * t4.w;
                    h2 += h4.x * h4.x + h4.y * h4.y + h4.z * h4.z + h4.w * h4.w;
                    __nv_bfloat162 a0, b0, a1, b1;
                    split2(t4.x, t4.y, a0, b0);
                    split2(t4.z, t4.w, a1, b1);
                    *(__nv_bfloat162*)(pth + f * 8)     = a0;
                    *(__nv_bfloat162*)(pth + f * 8 + 4) = a1;
                    *(__nv_bfloat162*)(ptl + f * 8)     = b0;
                    *(__nv_bfloat162*)(ptl + f * 8 + 4) = b1;
                    *(float4*)(phh + f * 4) = h4;
                }
            } else if (r < 16) {
                // zero-pad T rows so pad scores stay finite (never emitted)
                char* pth = Thi + r * KPB + half * 64 * 2;
                char* ptl = Tlo + r * KPB + half * 64 * 2;
#pragma unroll 4
                for (int f = 0; f < 16; f++) {
                    *(float2*)(pth + f * 8) = make_float2(0.f, 0.f);
                    *(float2*)(ptl + f * 8) = make_float2(0.f, 0.f);
                }
            }
        }
        __syncwarp();

        // Y = T . R^T  via 3-term bf16-split HMMA; acc[nt*4+j]
        float acc[64];
#pragma unroll
        for (int j = 0; j < 64; j++) acc[j] = 0.f;

#pragma unroll 2
        for (int kt = 0; kt < 8; kt++) {
            const int ka = kt * 16 + 2 * tig;
            uint32_t ah0 = *(const uint32_t*)(Thi + gr * KPB + ka * 2);
            uint32_t ah1 = *(const uint32_t*)(Thi + (gr + 8) * KPB + ka * 2);
            uint32_t ah2 = *(const uint32_t*)(Thi + gr * KPB + (ka + 8) * 2);
            uint32_t ah3 = *(const uint32_t*)(Thi + (gr + 8) * KPB + (ka + 8) * 2);
            uint32_t al0 = *(const uint32_t*)(Tlo + gr * KPB + ka * 2);
            uint32_t al1 = *(const uint32_t*)(Tlo + (gr + 8) * KPB + ka * 2);
            uint32_t al2 = *(const uint32_t*)(Tlo + gr * KPB + (ka + 8) * 2);
            uint32_t al3 = *(const uint32_t*)(Tlo + (gr + 8) * KPB + (ka + 8) * 2);
#pragma unroll
            for (int nt = 0; nt < 16; nt++) {
                const int n = nt * 8 + gr;
                uint32_t bh0 = *(const uint32_t*)(Rhi + n * KPB + ka * 2);
                uint32_t bh1 = *(const uint32_t*)(Rhi + n * KPB + (ka + 8) * 2);
                uint32_t bl0 = *(const uint32_t*)(Rlo + n * KPB + ka * 2);
                uint32_t bl1 = *(const uint32_t*)(Rlo + n * KPB + (ka + 8) * 2);
                float* c = acc + nt * 4;
                mma_bf16(c[0], c[1], c[2], c[3], ah0, ah1, ah2, ah3, bh0, bh1);
                mma_bf16(c[0], c[1], c[2], c[3], ah0, ah1, ah2, ah3, bl0, bl1);
                mma_bf16(c[0], c[1], c[2], c[3], al0, al1, al2, al3, bh0, bh1);
            }
        }

        // epilogue: score[m] = sum_n H[m][n] * Y[m][n]
        float s0 = 0.f, s1 = 0.f;
#pragma unroll
        for (int nt = 0; nt < 16; nt++) {
            const int cn = nt * 8 + 2 * tig;
            float2 hA = *(const float2*)(Hw + gr * HP + cn);
            float2 hB = *(const float2*)(Hw + (gr + 8) * HP + cn);
            s0 += hA.x * acc[nt * 4 + 0] + hA.y * acc[nt * 4 + 1];
            s1 += hB.x * acc[nt * 4 + 2] + hB.y * acc[nt * 4 + 3];
        }
        s0 += __shfl_xor_sync(0xffffffffu, s0, 1);
        s0 += __shfl_xor_sync(0xffffffffu, s0, 2);
        s1 += __shfl_xor_sync(0xffffffffu, s1, 1);
        s1 += __shfl_xor_sync(0xffffffffu, s1, 2);
        if (tig == 0) {
            if (gr < ne) {
                int i = bucket[base + gr];
                out[1 + i] = s0;
                float d = s0 - labels[i];
                sq += d * d;
            }
            if (gr + 8 < ne) {
                int i = bucket[base + gr + 8];
                out[1 + i] = s1;
                float d = s1 - labels[i];
                sq += d * d;
            }
        }
        __syncwarp();
    }

    // ---- loss partials ----
    h2 = warpSum(h2);
    t2 = warpSum(t2);
    sq = warpSum(sq);
    if (lane == 0) {
        atomicAdd(&sH2, h2);
        atomicAdd(&sT2, t2);
        atomicAdd(&sE2, sq);
    }
    __syncthreads();
    if (tid == 0) {
        atomicAdd(&g_acc[0], sH2);
        atomicAdd(&g_acc[1], sT2);
        atomicAdd(&g_acc[2], sR2 * (float)count);
        atomicAdd(&g_acc[3], sE2);
    }
}

// computes loss AND resets accumulators for the next graph replay
__global__ void finalize_kernel(float* __restrict__ out) {
    int t = blockIdx.x * blockDim.x + threadIdx.x;
    if (t == 0) {
        const float invBD  = 1.0f / ((float)BATCH * (float)DIM);
        const float invBDD = 1.0f / ((float)BATCH * (float)DIM * (float)DIM);
        float norms = (g_acc[0] * invBD + g_acc[1] * invBD + g_acc[2] * invBDD) * (1.0f / 3.0f);
        out[0] = g_acc[3] / (float)BATCH + ALPHA * norms;
        g_acc[0] = 0.f; g_acc[1] = 0.f; g_acc[2] = 0.f; g_acc[3] = 0.f;
    }
    if (t < NREL) g_cnt[t] = 0;
}

extern "C" void kernel_launch(void* const* d_in, const int* in_sizes, int n_in,
                              void* d_out, int out_size)
{
    const int*   h_idx  = (const int*)d_in[0];
    const int*   r_idx  = (const int*)d_in[1];
    const int*   t_idx  = (const int*)d_in[2];
    const float* labels = (const float*)d_in[3];
    const float* ent_w  = (const float*)d_in[4];
    const float* rel_w  = (const float*)d_in[5];
    float*       out    = (float*)d_out;

    cudaFuncSetAttribute(rescal_main,
                         cudaFuncAttributeMaxDynamicSharedMemorySize, SMEM_TOTAL);

    bucket_kernel<<<(BATCH + 255) / 256, 256>>>(r_idx);
    rescal_main<<<NREL, 128, SMEM_TOTAL>>>(h_idx, t_idx, labels, ent_w, rel_w, out);
    finalize_kernel<<<1, 512>>>(out);
}